// round 9
// baseline (speedup 1.0000x reference)
#include <cuda_runtime.h>
#include <cuda_fp16.h>
#include <cstdint>

// Flow_68015102099543: implicit-GEMM conv3x3 via warp mma (fp16 in, fp32 accum).
// Batch-pipelined double-buffered staging; warp tile = 4 rows x 16 px (dy-reuse
// of B fragments at 1.125 wf/px); 128-thread CTAs (16x16 tile), ~6 CTAs/SM.

#define HH 450
#define WW 480
#define HW (HH * WW)

#define CTA_H 16
#define CTA_W 16
#define HSX 18          // staged rows (CTA_H + 2)
#define WSS 18          // staged w positions (CTA_W + 2)
#define NPOS (HSX * WSS * 2)   // 648 uint4 slots per buffer
#define ROWB (WSS * 32)        // 576 B per staged row

__device__ __forceinline__ uint32_t smem_u32(const void* p) {
    return (uint32_t)__cvta_generic_to_shared(p);
}

__device__ __forceinline__ void ldsm_x4(uint32_t& r0, uint32_t& r1, uint32_t& r2, uint32_t& r3,
                                        uint32_t a) {
    asm volatile("ldmatrix.sync.aligned.m8n8.x4.shared.b16 {%0,%1,%2,%3}, [%4];"
                 : "=r"(r0), "=r"(r1), "=r"(r2), "=r"(r3) : "r"(a));
}

__device__ __forceinline__ void mma_fp16(float* d, const uint32_t* a,
                                         uint32_t b0, uint32_t b1) {
    asm volatile("mma.sync.aligned.m16n8k16.row.col.f32.f16.f16.f32 "
                 "{%0,%1,%2,%3}, {%4,%5,%6,%7}, {%8,%9}, {%0,%1,%2,%3};"
                 : "+f"(d[0]), "+f"(d[1]), "+f"(d[2]), "+f"(d[3])
                 : "r"(a[0]), "r"(a[1]), "r"(a[2]), "r"(a[3]), "r"(b0), "r"(b1));
}

// Load one staging position (8 channel floats) for batch bb.
__device__ __forceinline__ void ldg_pos(float* v, const float* __restrict__ x,
                                        int bb, int h0, int w0, int u) {
    if (u >= NPOS) return;
    int h_s = u / (WSS * 2);
    int rem = u - h_s * (WSS * 2);
    int w_s = rem >> 1;
    int half_ = rem & 1;
    int gh = h0 - 1 + h_s;
    int gw = w0 - 1 + w_s;
    bool ok = ((unsigned)gh < (unsigned)HH) && ((unsigned)gw < (unsigned)WW);
    const float* p = x + ((size_t)(bb * 16 + half_ * 8) * HW) + gh * WW + gw;
#pragma unroll
    for (int cc = 0; cc < 8; cc++)
        v[cc] = ok ? __ldg(p + (size_t)cc * HW) : 0.0f;
}

// Convert + store one staging position (swizzled) into buffer.
__device__ __forceinline__ void sts_pos(uint4* buf, const float* v, int u) {
    if (u >= NPOS) return;
    int h_s = u / (WSS * 2);
    int rem = u - h_s * (WSS * 2);
    int w_s = rem >> 1;
    int half_ = rem & 1;
    uint32_t pk[4];
#pragma unroll
    for (int cc = 0; cc < 4; cc++) {
        __half2 p = __floats2half2_rn(v[2 * cc], v[2 * cc + 1]);
        pk[cc] = *(uint32_t*)&p;
    }
    buf[(h_s * WSS + w_s) * 2 + (half_ ^ ((w_s >> 2) & 1))] =
        make_uint4(pk[0], pk[1], pk[2], pk[3]);
}

__global__ void __launch_bounds__(128, 5) flow_p4_kernel(
    const float* __restrict__ x,      // [4,16,450,480]
    const float* __restrict__ comb,   // [16,144]
    const float* __restrict__ bias,   // [16]
    float* __restrict__ out)          // [4,16,450,480]
{
    __shared__ uint4 xs4[2][NPOS];    // 2 x 10368 B
    __shared__ uint4 ws4[9 * 16 * 2]; // 4608 B

    const int tid = threadIdx.x;
    const int h0 = blockIdx.y * CTA_H;
    const int w0 = blockIdx.x * CTA_W;

    // ---- stage weights once (fp32 -> fp16) ----
    for (int idx = tid; idx < 9 * 16 * 16; idx += 128) {
        int i = idx >> 8, o = (idx >> 4) & 15, c = idx & 15;
        float v = comb[o * 144 + i * 16 + c];
        int half_ = c >> 3;
        int phys = (i * 16 + o) * 2 + (half_ ^ ((o >> 2) & 1));
        ((__half*)ws4)[phys * 8 + (c & 7)] = __float2half(v);
    }

    // ---- stage batch 0 ----
    {
        float v[8];
#pragma unroll
        for (int k = 0; k < 6; k++) {
            int u = k * 128 + tid;
            ldg_pos(v, x, 0, h0, w0, u);
            sts_pos(xs4[0], v, u);
        }
    }
    __syncthreads();

    const int wid  = tid >> 5;     // warp 0..3 -> rows h0 + wid*4 .. +3
    const int lane = tid & 31;

    const int og = lane >> 2;
    const float b0v = __ldg(bias + og);
    const float b8v = __ldg(bias + 8 + og);

    const uint32_t wbase = smem_u32(ws4);
    // A-frag lane addressing (proven scheme)
    const int o_l   = ((lane >> 3) & 1) * 8 + (lane & 7);
    const int ahalf = (lane >> 4) & 1;
    const uint32_t aoff = (uint32_t)((o_l * 2 + (ahalf ^ ((o_l >> 2) & 1))) * 16);
    // B-frag lane addressing
    const int bp    = lane & 7;
    const int bhalf = (lane >> 3) & 1;

#pragma unroll
    for (int bb = 0; bb < 4; bb++) {
        const int cur = bb & 1;
        uint4* nbuf = xs4[1 - cur];

        float v[8];
        if (bb < 3) ldg_pos(v, x, bb + 1, h0, w0, tid);          // chunk 0

        // accumulators: acc[r][g][0..3]
        float acc[4][2][4];
#pragma unroll
        for (int r = 0; r < 4; r++)
#pragma unroll
            for (int g = 0; g < 2; g++) {
                acc[r][g][0] = b0v; acc[r][g][1] = b0v;
                acc[r][g][2] = b8v; acc[r][g][3] = b8v;
            }

        const uint32_t xb = smem_u32(xs4[cur]) + (uint32_t)(wid * 4) * ROWB;

#pragma unroll
        for (int dx = 0; dx < 3; dx++) {
            uint32_t a[3][4];
#pragma unroll
            for (int dy = 0; dy < 3; dy++)
                ldsm_x4(a[dy][0], a[dy][1], a[dy][2], a[dy][3],
                        wbase + (uint32_t)(dy * 3 + dx) * 512u + aoff);

            // lane-resident B column offset (covers both 8-px groups via x4)
            const int w_sA = ((lane >> 4) & 1) * 8 + dx + bp;
            const uint32_t colA =
                (uint32_t)((w_sA * 2 + (bhalf ^ ((w_sA >> 2) & 1))) * 16);

#pragma unroll
            for (int ii = 0; ii < 6; ii++) {
                uint32_t q0, q1, q2, q3;
                ldsm_x4(q0, q1, q2, q3, xb + (uint32_t)(ii * ROWB) + colA);
                // input row ii serves output rows r = ii - dy, r in [0,4)
#pragma unroll
                for (int dy = 0; dy < 3; dy++) {
                    const int r = ii - dy;
                    if (r >= 0 && r < 4) {
                        mma_fp16(acc[r][0], a[dy], q0, q1);
                        mma_fp16(acc[r][1], a[dy], q2, q3);
                    }
                }
            }

            if (bb < 3) {           // staged chunk rotation inside dx loop
                sts_pos(nbuf, v, dx * 128 + tid);
                ldg_pos(v, x, bb + 1, h0, w0, (dx + 1) * 128 + tid);
            }
        }

        if (bb < 3) {               // chunk 3
            sts_pos(nbuf, v, 384 + tid);
            ldg_pos(v, x, bb + 1, h0, w0, 512 + tid);
        }

        // ---- epilogue store for batch bb ----
        const int pw = (lane & 3) * 2;
#pragma unroll
        for (int r = 0; r < 4; r++) {
            const int h = h0 + wid * 4 + r;
            if (h < HH) {
                float* op0 = out + ((((size_t)bb * 16 + og) * HH + h) * WW + w0 + pw);
                float* op8 = op0 + (size_t)8 * HW;
#pragma unroll
                for (int g = 0; g < 2; g++) {
                    float2 u01; u01.x = acc[r][g][0]; u01.y = acc[r][g][1];
                    float2 u23; u23.x = acc[r][g][2]; u23.y = acc[r][g][3];
                    *(float2*)(op0 + g * 8) = u01;
                    *(float2*)(op8 + g * 8) = u23;
                }
            }
        }

        if (bb < 3) {               // chunks 4,5 (chunk 5 tiny: 8 positions)
            sts_pos(nbuf, v, 512 + tid);
            float v5[8];
            ldg_pos(v5, x, bb + 1, h0, w0, 640 + tid);
            sts_pos(nbuf, v5, 640 + tid);
        }
        __syncthreads();
    }
}

extern "C" void kernel_launch(void* const* d_in, const int* in_sizes, int n_in,
                              void* d_out, int out_size) {
    const float* x    = (const float*)d_in[0];
    const float* comb = (const float*)d_in[1];
    const float* bias = (const float*)d_in[2];
    float* out = (float*)d_out;

    dim3 grid(WW / CTA_W, (HH + CTA_H - 1) / CTA_H, 1);   // (30, 29) = 870 CTAs
    flow_p4_kernel<<<grid, 128>>>(x, comb, bias, out);
}

// round 10
// speedup vs baseline: 1.1395x; 1.1395x over previous
#include <cuda_runtime.h>
#include <cuda_fp16.h>
#include <cstdint>

// Flow_68015102099543: implicit-GEMM conv3x3 via warp mma (fp16 in, fp32 accum).
// Pixel-permuted B-fragment columns (f = {0,1,4,5,8,9,12,13}) make each lane's
// D registers hold 4 CONTIGUOUS output pixels -> STG.128 coalesced epilogue
// (64B/plane segments, half the store wavefronts). Gapped smem layout
// sigma(w) = w + 2*(w>>2) with swizzle half^((sigma>>2)&1) keeps ldmatrix and
// STS bank-conflict-free for all shift windows (verified by hand).

#define HH 450
#define WW 480
#define HW (HH * WW)

#define CTA_H 8         // 8 warps x 1 output row
#define CTA_W 48        // 3 pixel-pairs of 16
#define HSX 10          // staged rows (CTA_H + 2)
#define NWS 50          // staged w positions (CTA_W + 2)
#define ROWU 148        // 16B units per staged row (sigma(49)=73 -> 147 max)
#define ROWB (ROWU * 16)
#define UIDX 104        // staging index stride per row (multiple of 8, >= 100)

__device__ __forceinline__ uint32_t smem_u32(const void* p) {
    return (uint32_t)__cvta_generic_to_shared(p);
}

__device__ __forceinline__ void ldsm_x4(uint32_t& r0, uint32_t& r1, uint32_t& r2, uint32_t& r3,
                                        uint32_t a) {
    asm volatile("ldmatrix.sync.aligned.m8n8.x4.shared.b16 {%0,%1,%2,%3}, [%4];"
                 : "=r"(r0), "=r"(r1), "=r"(r2), "=r"(r3) : "r"(a));
}

__device__ __forceinline__ void mma_fp16(float* d, const uint32_t* a,
                                         uint32_t b0, uint32_t b1) {
    asm volatile("mma.sync.aligned.m16n8k16.row.col.f32.f16.f16.f32 "
                 "{%0,%1,%2,%3}, {%4,%5,%6,%7}, {%8,%9}, {%0,%1,%2,%3};"
                 : "+f"(d[0]), "+f"(d[1]), "+f"(d[2]), "+f"(d[3])
                 : "r"(a[0]), "r"(a[1]), "r"(a[2]), "r"(a[3]), "r"(b0), "r"(b1));
}

// staged placement: 16B unit for (w_s, half)
__device__ __forceinline__ uint32_t unit_of(int w_s, int half_) {
    int sg = w_s + 2 * (w_s >> 2);
    return (uint32_t)(2 * sg + (half_ ^ ((sg >> 2) & 1)));
}

__global__ void __launch_bounds__(256, 5) flow_perm_kernel(
    const float* __restrict__ x,      // [4,16,450,480]
    const float* __restrict__ comb,   // [16,144]
    const float* __restrict__ bias,   // [16]
    float* __restrict__ out)          // [4,16,450,480]
{
    __shared__ uint4 xs4[HSX * ROWU];         // 23680 B
    __shared__ uint4 ws4[9 * 16 * 2];         // 4608 B

    const int tid = threadIdx.x;
    const int b  = blockIdx.z;
    const int h0 = blockIdx.y * CTA_H;
    const int w0 = blockIdx.x * CTA_W;

    // ---- stage weights (fp32 -> fp16), proven scheme ----
    for (int idx = tid; idx < 9 * 16 * 16; idx += 256) {
        int i = idx >> 8, o = (idx >> 4) & 15, c = idx & 15;
        float v = comb[o * 144 + i * 16 + c];
        int half_ = c >> 3;
        int phys = (i * 16 + o) * 2 + (half_ ^ ((o >> 2) & 1));
        ((__half*)ws4)[phys * 8 + (c & 7)] = __float2half(v);
    }

    // ---- stage x tile: rows h0-1..h0+8, cols w0-1..w0+48, zero-padded ----
    for (int k = 0; k < 5; k++) {
        int u = k * 256 + tid;
        if (u >= HSX * UIDX) break;
        int h_s = u / UIDX;
        int rem = u - h_s * UIDX;
        int w_s = rem >> 1;
        int half_ = rem & 1;
        if (w_s >= NWS) continue;
        int gh = h0 - 1 + h_s;
        int gw = w0 - 1 + w_s;
        bool ok = ((unsigned)gh < (unsigned)HH) && ((unsigned)gw < (unsigned)WW);
        const float* xp = x + (((size_t)(b * 16 + half_ * 8) * HH + gh) * WW + gw);
        float v[8];
#pragma unroll
        for (int cc = 0; cc < 8; cc++)
            v[cc] = ok ? __ldg(xp + (size_t)cc * HW) : 0.0f;
        uint32_t pk[4];
#pragma unroll
        for (int cc = 0; cc < 4; cc++) {
            __half2 p = __floats2half2_rn(v[2 * cc], v[2 * cc + 1]);
            pk[cc] = *(uint32_t*)&p;
        }
        xs4[h_s * ROWU + unit_of(w_s, half_)] = make_uint4(pk[0], pk[1], pk[2], pk[3]);
    }
    __syncthreads();

    const int wid  = tid >> 5;
    const int lane = tid & 31;
    const int h = h0 + wid;
    if (h >= HH) return;          // whole-warp exit; no further barriers

    // accumulators: accA/accB[pair][0..3] -> (o=lane>>2, o+8) x 2 pixel cols
    const int og = lane >> 2;
    const float b0v = __ldg(bias + og);
    const float b8v = __ldg(bias + 8 + og);
    float accA[3][4], accB[3][4];
#pragma unroll
    for (int p = 0; p < 3; p++) {
        accA[p][0] = b0v; accA[p][1] = b0v; accA[p][2] = b8v; accA[p][3] = b8v;
        accB[p][0] = b0v; accB[p][1] = b0v; accB[p][2] = b8v; accB[p][3] = b8v;
    }

    const uint32_t wbase = smem_u32(ws4);
    const uint32_t xbase = smem_u32(xs4);

    // A-frag lane addressing (proven scheme)
    const int o_l   = ((lane >> 3) & 1) * 8 + (lane & 7);
    const int ahalf = (lane >> 4) & 1;
    const uint32_t aoff = (uint32_t)((o_l * 2 + (ahalf ^ ((o_l >> 2) & 1))) * 16);

    // B-frag lane params: bp row index, qset = matrix pair (perm vs perm+2), c-half
    const int bp    = lane & 7;
    const int fbp   = (bp & 1) | ((bp >> 1) << 2);   // f = {0,1,4,5,8,9,12,13}
    const int qset  = (lane >> 4) & 1;               // +0 / +2 pixel offset
    const int bhalf = (lane >> 3) & 1;

#pragma unroll
    for (int i = 0; i < 9; i++) {
        const int dy = i / 3, dx = i % 3;
        uint32_t a[4];
        ldsm_x4(a[0], a[1], a[2], a[3], wbase + (uint32_t)i * 512u + aoff);
        const uint32_t rowoff = (uint32_t)((wid + dy) * ROWB);
#pragma unroll
        for (int p = 0; p < 3; p++) {
            const int w_s = p * 16 + dx + fbp + 2 * qset;
            const uint32_t addr = xbase + rowoff + unit_of(w_s, bhalf) * 16u;
            uint32_t r0, r1, r2, r3;
            ldsm_x4(r0, r1, r2, r3, addr);    // m0/m1: perm set c-halves, m2/m3: +2 set
            mma_fp16(accA[p], a, r0, r1);
            mma_fp16(accB[p], a, r2, r3);
        }
    }

    // ---- coalesced epilogue: each lane stores float4 = 4 contiguous pixels ----
    const int j = lane & 3;
    float* op0 = out + ((((size_t)b * 16 + og) * HH + h) * WW + w0 + 4 * j);
    float* op8 = op0 + (size_t)8 * HW;
#pragma unroll
    for (int p = 0; p < 3; p++) {
        float4 v0; v0.x = accA[p][0]; v0.y = accA[p][1]; v0.z = accB[p][0]; v0.w = accB[p][1];
        float4 v8; v8.x = accA[p][2]; v8.y = accA[p][3]; v8.z = accB[p][2]; v8.w = accB[p][3];
        *(float4*)(op0 + p * 16) = v0;
        *(float4*)(op8 + p * 16) = v8;
    }
}

extern "C" void kernel_launch(void* const* d_in, const int* in_sizes, int n_in,
                              void* d_out, int out_size) {
    const float* x    = (const float*)d_in[0];
    const float* comb = (const float*)d_in[1];
    const float* bias = (const float*)d_in[2];
    float* out = (float*)d_out;

    dim3 grid(WW / CTA_W, (HH + CTA_H - 1) / CTA_H, 4);   // (10, 57, 4)
    flow_perm_kernel<<<grid, 256>>>(x, comb, bias, out);
}

// round 11
// speedup vs baseline: 1.1429x; 1.0030x over previous
#include <cuda_runtime.h>
#include <cuda_fp16.h>
#include <cstdint>

// Flow_68015102099543: implicit-GEMM conv3x3 via warp mma (fp16 in, fp32 accum).
// R10 kernel (pixel-permuted B columns -> per-lane contiguous float4 outputs,
// gapped conflict-free smem) with ONE change: the epilogue uses streaming
// stores (st.global.wt) so the write-once output stream bypasses L2 and stops
// contending with the x read stream.

#define HH 450
#define WW 480
#define HW (HH * WW)

#define CTA_H 8         // 8 warps x 1 output row
#define CTA_W 48        // 3 pixel-pairs of 16
#define HSX 10          // staged rows (CTA_H + 2)
#define NWS 50          // staged w positions (CTA_W + 2)
#define ROWU 148        // 16B units per staged row (sigma(49)=73 -> 147 max)
#define ROWB (ROWU * 16)
#define UIDX 104        // staging index stride per row (multiple of 8, >= 100)

__device__ __forceinline__ uint32_t smem_u32(const void* p) {
    return (uint32_t)__cvta_generic_to_shared(p);
}

__device__ __forceinline__ void ldsm_x4(uint32_t& r0, uint32_t& r1, uint32_t& r2, uint32_t& r3,
                                        uint32_t a) {
    asm volatile("ldmatrix.sync.aligned.m8n8.x4.shared.b16 {%0,%1,%2,%3}, [%4];"
                 : "=r"(r0), "=r"(r1), "=r"(r2), "=r"(r3) : "r"(a));
}

__device__ __forceinline__ void mma_fp16(float* d, const uint32_t* a,
                                         uint32_t b0, uint32_t b1) {
    asm volatile("mma.sync.aligned.m16n8k16.row.col.f32.f16.f16.f32 "
                 "{%0,%1,%2,%3}, {%4,%5,%6,%7}, {%8,%9}, {%0,%1,%2,%3};"
                 : "+f"(d[0]), "+f"(d[1]), "+f"(d[2]), "+f"(d[3])
                 : "r"(a[0]), "r"(a[1]), "r"(a[2]), "r"(a[3]), "r"(b0), "r"(b1));
}

__device__ __forceinline__ void stwt_f4(float* p, float a, float b, float c, float d) {
    asm volatile("st.global.wt.v4.f32 [%0], {%1, %2, %3, %4};"
                 :: "l"(p), "f"(a), "f"(b), "f"(c), "f"(d) : "memory");
}

// staged placement: 16B unit for (w_s, half)
__device__ __forceinline__ uint32_t unit_of(int w_s, int half_) {
    int sg = w_s + 2 * (w_s >> 2);
    return (uint32_t)(2 * sg + (half_ ^ ((sg >> 2) & 1)));
}

__global__ void __launch_bounds__(256, 5) flow_wt_kernel(
    const float* __restrict__ x,      // [4,16,450,480]
    const float* __restrict__ comb,   // [16,144]
    const float* __restrict__ bias,   // [16]
    float* __restrict__ out)          // [4,16,450,480]
{
    __shared__ uint4 xs4[HSX * ROWU];         // 23680 B
    __shared__ uint4 ws4[9 * 16 * 2];         // 4608 B

    const int tid = threadIdx.x;
    const int b  = blockIdx.z;
    const int h0 = blockIdx.y * CTA_H;
    const int w0 = blockIdx.x * CTA_W;

    // ---- stage weights (fp32 -> fp16), proven scheme ----
    for (int idx = tid; idx < 9 * 16 * 16; idx += 256) {
        int i = idx >> 8, o = (idx >> 4) & 15, c = idx & 15;
        float v = comb[o * 144 + i * 16 + c];
        int half_ = c >> 3;
        int phys = (i * 16 + o) * 2 + (half_ ^ ((o >> 2) & 1));
        ((__half*)ws4)[phys * 8 + (c & 7)] = __float2half(v);
    }

    // ---- stage x tile: rows h0-1..h0+8, cols w0-1..w0+48, zero-padded ----
    for (int k = 0; k < 5; k++) {
        int u = k * 256 + tid;
        if (u >= HSX * UIDX) break;
        int h_s = u / UIDX;
        int rem = u - h_s * UIDX;
        int w_s = rem >> 1;
        int half_ = rem & 1;
        if (w_s >= NWS) continue;
        int gh = h0 - 1 + h_s;
        int gw = w0 - 1 + w_s;
        bool ok = ((unsigned)gh < (unsigned)HH) && ((unsigned)gw < (unsigned)WW);
        const float* xp = x + (((size_t)(b * 16 + half_ * 8) * HH + gh) * WW + gw);
        float v[8];
#pragma unroll
        for (int cc = 0; cc < 8; cc++)
            v[cc] = ok ? __ldg(xp + (size_t)cc * HW) : 0.0f;
        uint32_t pk[4];
#pragma unroll
        for (int cc = 0; cc < 4; cc++) {
            __half2 p = __floats2half2_rn(v[2 * cc], v[2 * cc + 1]);
            pk[cc] = *(uint32_t*)&p;
        }
        xs4[h_s * ROWU + unit_of(w_s, half_)] = make_uint4(pk[0], pk[1], pk[2], pk[3]);
    }
    __syncthreads();

    const int wid  = tid >> 5;
    const int lane = tid & 31;
    const int h = h0 + wid;
    if (h >= HH) return;          // whole-warp exit; no further barriers

    // accumulators: accA/accB[pair][0..3] -> (o=lane>>2, o+8) x 2 pixel cols
    const int og = lane >> 2;
    const float b0v = __ldg(bias + og);
    const float b8v = __ldg(bias + 8 + og);
    float accA[3][4], accB[3][4];
#pragma unroll
    for (int p = 0; p < 3; p++) {
        accA[p][0] = b0v; accA[p][1] = b0v; accA[p][2] = b8v; accA[p][3] = b8v;
        accB[p][0] = b0v; accB[p][1] = b0v; accB[p][2] = b8v; accB[p][3] = b8v;
    }

    const uint32_t wbase = smem_u32(ws4);
    const uint32_t xbase = smem_u32(xs4);

    // A-frag lane addressing (proven scheme)
    const int o_l   = ((lane >> 3) & 1) * 8 + (lane & 7);
    const int ahalf = (lane >> 4) & 1;
    const uint32_t aoff = (uint32_t)((o_l * 2 + (ahalf ^ ((o_l >> 2) & 1))) * 16);

    // B-frag lane params: bp row index, qset = matrix pair (perm vs perm+2), c-half
    const int bp    = lane & 7;
    const int fbp   = (bp & 1) | ((bp >> 1) << 2);   // f = {0,1,4,5,8,9,12,13}
    const int qset  = (lane >> 4) & 1;               // +0 / +2 pixel offset
    const int bhalf = (lane >> 3) & 1;

#pragma unroll
    for (int i = 0; i < 9; i++) {
        const int dy = i / 3, dx = i % 3;
        uint32_t a[4];
        ldsm_x4(a[0], a[1], a[2], a[3], wbase + (uint32_t)i * 512u + aoff);
        const uint32_t rowoff = (uint32_t)((wid + dy) * ROWB);
#pragma unroll
        for (int p = 0; p < 3; p++) {
            const int w_s = p * 16 + dx + fbp + 2 * qset;
            const uint32_t addr = xbase + rowoff + unit_of(w_s, bhalf) * 16u;
            uint32_t r0, r1, r2, r3;
            ldsm_x4(r0, r1, r2, r3, addr);    // m0/m1: perm set c-halves, m2/m3: +2 set
            mma_fp16(accA[p], a, r0, r1);
            mma_fp16(accB[p], a, r2, r3);
        }
    }

    // ---- coalesced streaming epilogue: float4 = 4 contiguous pixels, L2-bypass ----
    const int j = lane & 3;
    float* op0 = out + ((((size_t)b * 16 + og) * HH + h) * WW + w0 + 4 * j);
    float* op8 = op0 + (size_t)8 * HW;
#pragma unroll
    for (int p = 0; p < 3; p++) {
        stwt_f4(op0 + p * 16, accA[p][0], accA[p][1], accB[p][0], accB[p][1]);
        stwt_f4(op8 + p * 16, accA[p][2], accA[p][3], accB[p][2], accB[p][3]);
    }
}

extern "C" void kernel_launch(void* const* d_in, const int* in_sizes, int n_in,
                              void* d_out, int out_size) {
    const float* x    = (const float*)d_in[0];
    const float* comb = (const float*)d_in[1];
    const float* bias = (const float*)d_in[2];
    float* out = (float*)d_out;

    dim3 grid(WW / CTA_W, (HH + CTA_H - 1) / CTA_H, 4);   // (10, 57, 4)
    flow_wt_kernel<<<grid, 256>>>(x, comb, bias, out);
}